// round 3
// baseline (speedup 1.0000x reference)
#include <cuda_runtime.h>
#include <cstdint>

#define NQ   4
#define DIM  16
#define NC   4
#define BLK  256
#define CHUNK 64
#define PITCH 148                  // floats/row in smem; 148 mod 32 = 20 -> LDS.128 conflict-free
#define NCHUNKS 16                 // rows per block = 16*64 = 1024
#define ROWS_PER_BLOCK (NCHUNKS * CHUNK)
#define SMEM_BYTES (2 * CHUNK * PITCH * 4)   // 75776 B double buffer

__device__ double g_acc[8];        // [0..3]=sum logit_c, [4..7]=sum logit_c^2
__device__ float  g_scale[NC];
__device__ float  g_shift[NC];
__device__ unsigned g_cnt;
__device__ int g_flag;

__global__ void k_init() {
    if (threadIdx.x < 8) g_acc[threadIdx.x] = 0.0;
    if (threadIdx.x == 0) { g_cnt = 0u; g_flag = 0; }
}

__device__ __forceinline__ void cp16(float* dst_smem, const float4* src) {
    unsigned d = (unsigned)__cvta_generic_to_shared(dst_smem);
    asm volatile("cp.async.cg.shared.global [%0], [%1], 16;\n" :: "r"(d), "l"(src));
}

__global__ void __launch_bounds__(BLK, 2) k_persist(
    const float* __restrict__ x,      // [B,144]
    const float* __restrict__ wts,    // [8]
    const float* __restrict__ W,      // [4,4]
    const float* __restrict__ bias,   // [4]
    const float* __restrict__ gamma,  // [4]
    const float* __restrict__ beta,   // [4]
    float* __restrict__ out,          // [B,4]
    int B, float invB)
{
    extern __shared__ float sbuf[];   // [2][CHUNK*PITCH]
    const int t = threadIdx.x;
    const size_t rowbase = (size_t)blockIdx.x * ROWS_PER_BLOCK;

    // RY weight angles (broadcast)
    float wc[8], ws[8];
    #pragma unroll
    for (int i = 0; i < 8; i++) __sincosf(wts[i] * 0.5f, &ws[i], &wc[i]);
    float Wr[16], bi[4];
    #pragma unroll
    for (int i = 0; i < 16; i++) Wr[i] = W[i];
    #pragma unroll
    for (int i = 0; i < 4; i++)  bi[i] = bias[i];

    float lg[4][4];                   // held logits (4 iters x 4 classes)
    float sum0=0.f,sum1=0.f,sum2=0.f,sum3=0.f, sq0=0.f,sq1=0.f,sq2=0.f,sq3=0.f;
    float s0=0.f, s1=0.f, s2=0.f, s3=0.f;   // pooled quadrant sums for my current row

    // ---- issue chunk 0 ----
    {
        const float4* src = (const float4*)(x + rowbase * 144);
        float* dst = sbuf;
        #pragma unroll
        for (int k = 0; k < 9; k++) {
            int idx = t + k * BLK;
            int row = idx / 36, col4 = idx % 36;
            cp16(dst + row * PITCH + col4 * 4, src + idx);
        }
        asm volatile("cp.async.commit_group;\n");
    }

    #pragma unroll 1
    for (int c = 0; c < NCHUNKS; c++) {
        if (c + 1 < NCHUNKS) {
            const float4* src = (const float4*)(x + (rowbase + (size_t)(c + 1) * CHUNK) * 144);
            float* dst = sbuf + ((c + 1) & 1) * (CHUNK * PITCH);
            #pragma unroll
            for (int k = 0; k < 9; k++) {
                int idx = t + k * BLK;
                int row = idx / 36, col4 = idx % 36;
                cp16(dst + row * PITCH + col4 * 4, src + idx);
            }
            asm volatile("cp.async.commit_group;\n");
            asm volatile("cp.async.wait_group 1;\n");
        } else {
            asm volatile("cp.async.wait_group 0;\n");
        }
        __syncthreads();

        // owner threads of this chunk pool from smem
        if ((t >> 6) == (c & 3)) {
            const float* rp = sbuf + (c & 1) * (CHUNK * PITCH) + (t & 63) * PITCH;
            float a0=0.f, a1=0.f, a2=0.f, a3=0.f;
            #pragma unroll
            for (int r = 0; r < 12; r++) {
                float4 v0 = *(const float4*)&rp[r * 12 + 0];
                float4 v1 = *(const float4*)&rp[r * 12 + 4];
                float4 v2 = *(const float4*)&rp[r * 12 + 8];
                float left  = v0.x + v0.y + v0.z + v0.w + v1.x + v1.y;
                float right = v1.z + v1.w + v2.x + v2.y + v2.z + v2.w;
                if (r < 6) { a0 += left; a1 += right; }
                else       { a2 += left; a3 += right; }
            }
            s0 = a0; s1 = a1; s2 = a2; s3 = a3;
        }
        __syncthreads();

        if ((c & 3) == 3) {
            // every thread now has pooled sums for its row of iteration i = c/4
            const int i = c >> 2;
            const float inv72 = 1.f / 72.f;   // (1/36)*0.5
            float pc4[4], ps4[4];
            __sincosf(s0 * inv72, &ps4[0], &pc4[0]);
            __sincosf(s1 * inv72, &ps4[1], &pc4[1]);
            __sincosf(s2 * inv72, &ps4[2], &pc4[2]);
            __sincosf(s3 * inv72, &ps4[3], &pc4[3]);

            float re[DIM], im[DIM];
            #pragma unroll
            for (int k = 0; k < DIM; k++) {
                float m = ((k & 8) ? ps4[0] : pc4[0])
                        * ((k & 4) ? ps4[1] : pc4[1])
                        * ((k & 2) ? ps4[2] : pc4[2])
                        * ((k & 1) ? ps4[3] : pc4[3]);
                int pc = __popc(k) & 3;
                re[k] = (pc == 0) ? m : ((pc == 2) ? -m : 0.f);
                im[k] = (pc == 1) ? -m : ((pc == 3) ? m : 0.f);
            }
            int idx = 0;
            #pragma unroll
            for (int d = 0; d < 2; d++) {
                #pragma unroll
                for (int w = 0; w < NQ; w++) {
                    float cc = wc[idx], ss = ws[idx]; idx++;
                    int bit = 1 << (3 - w);
                    #pragma unroll
                    for (int k = 0; k < DIM; k++) {
                        if (!(k & bit)) {
                            int k1 = k | bit;
                            float r0 = re[k], r1 = re[k1];
                            re[k]  = cc * r0 - ss * r1;
                            re[k1] = ss * r0 + cc * r1;
                            float i0 = im[k], i1 = im[k1];
                            im[k]  = cc * i0 - ss * i1;
                            im[k1] = ss * i0 + cc * i1;
                        }
                    }
                }
                #pragma unroll
                for (int k = 0; k < DIM; k++) {
                    int par = (((k >> 3) & (k >> 2)) ^ ((k >> 2) & (k >> 1)) ^ ((k >> 1) & k)) & 1;
                    if (par) { re[k] = -re[k]; im[k] = -im[k]; }
                }
            }
            float q0=0.f, q1=0.f, q2=0.f, q3=0.f;
            #pragma unroll
            for (int k = 0; k < DIM; k++) {
                float p = re[k] * re[k] + im[k] * im[k];
                q0 += (k & 8) ? -p : p;
                q1 += (k & 4) ? -p : p;
                q2 += (k & 2) ? -p : p;
                q3 += (k & 1) ? -p : p;
            }
            #pragma unroll
            for (int cc2 = 0; cc2 < NC; cc2++) {
                float L = bi[cc2] + q0 * Wr[cc2*4+0] + q1 * Wr[cc2*4+1]
                                  + q2 * Wr[cc2*4+2] + q3 * Wr[cc2*4+3];
                lg[i][cc2] = L;
            }
            sum0 += lg[i][0]; sum1 += lg[i][1]; sum2 += lg[i][2]; sum3 += lg[i][3];
            sq0 += lg[i][0]*lg[i][0]; sq1 += lg[i][1]*lg[i][1];
            sq2 += lg[i][2]*lg[i][2]; sq3 += lg[i][3]*lg[i][3];
        }
    }

    // ---- block reduction of 8 partial sums ----
    float red[8] = {sum0,sum1,sum2,sum3,sq0,sq1,sq2,sq3};
    #pragma unroll
    for (int off = 16; off > 0; off >>= 1) {
        #pragma unroll
        for (int j = 0; j < 8; j++)
            red[j] += __shfl_down_sync(0xFFFFFFFFu, red[j], off);
    }
    __shared__ float rsm[8][BLK / 32];
    int lane = t & 31, warp = t >> 5;
    if (lane == 0) {
        #pragma unroll
        for (int j = 0; j < 8; j++) rsm[j][warp] = red[j];
    }
    __syncthreads();
    if (t < 8) {
        float acc = 0.f;
        #pragma unroll
        for (int wgi = 0; wgi < BLK / 32; wgi++) acc += rsm[t][wgi];
        atomicAdd(&g_acc[t], (double)acc);
        __threadfence();
    }
    __syncthreads();

    // ---- software grid barrier ----
    if (t == 0) {
        unsigned r = atomicAdd(&g_cnt, 1u);
        if (r == gridDim.x - 1u) {
            // last block: compute BN affine
            #pragma unroll
            for (int c2 = 0; c2 < NC; c2++) {
                double m = g_acc[c2] * (double)invB;
                double v = g_acc[4 + c2] * (double)invB - m * m;
                float inv = rsqrtf((float)v + 1e-5f);
                g_scale[c2] = gamma[c2] * inv;
                g_shift[c2] = beta[c2] - (float)m * inv * gamma[c2];
            }
            __threadfence();
            atomicExch(&g_flag, 1);
        } else {
            while (atomicAdd(&g_flag, 0) == 0) __nanosleep(128);
        }
    }
    __syncthreads();

    float sc[4], sh[4];
    #pragma unroll
    for (int c2 = 0; c2 < NC; c2++) {
        sc[c2] = *((volatile float*)&g_scale[c2]);
        sh[c2] = *((volatile float*)&g_shift[c2]);
    }

    // ---- write final normalized output (coalesced float4) ----
    float4* o4 = (float4*)out;
    #pragma unroll
    for (int i = 0; i < 4; i++) {
        float4 v = make_float4(lg[i][0]*sc[0]+sh[0], lg[i][1]*sc[1]+sh[1],
                               lg[i][2]*sc[2]+sh[2], lg[i][3]*sc[3]+sh[3]);
        o4[rowbase + (size_t)i * 256 + t] = v;
    }
}

extern "C" void kernel_launch(void* const* d_in, const int* in_sizes, int n_in,
                              void* d_out, int out_size) {
    const float* x     = (const float*)d_in[0];
    const float* wts   = (const float*)d_in[1];
    const float* W     = (const float*)d_in[2];
    const float* bias  = (const float*)d_in[3];
    const float* gamma = (const float*)d_in[4];
    const float* beta  = (const float*)d_in[5];
    float* out = (float*)d_out;

    int B = in_sizes[0] / 144;                 // 262144
    int grid = B / ROWS_PER_BLOCK;             // 256 blocks (co-resident: <= 2/SM * 148)

    cudaFuncSetAttribute(k_persist, cudaFuncAttributeMaxDynamicSharedMemorySize, SMEM_BYTES);

    k_init<<<1, 32>>>();
    k_persist<<<grid, BLK, SMEM_BYTES>>>(x, wts, W, bias, gamma, beta, out,
                                         B, 1.0f / (float)B);
}

// round 5
// speedup vs baseline: 1.0919x; 1.0919x over previous
#include <cuda_runtime.h>
#include <cstdint>

#define NQ   4
#define DIM  16
#define NC   4
#define BLK  256
#define WARPS_PER_BLK 8
#define GRID 148
#define WARPS_TOTAL (GRID * WARPS_PER_BLK)      // 1184
#define GROUP_ROWS 32
#define CHUNK_ROWS 16
#define ROW_PITCH 592                           // 576 + 16 pad: conflict-free LDS
#define CHUNK_BYTES (CHUNK_ROWS * ROW_PITCH)    // 9472
#define WARP_SMEM (2 * CHUNK_BYTES)             // 18944
#define SMEM_BYTES (WARPS_PER_BLK * WARP_SMEM)  // 151552
#define MAX_G 7                                 // ceil(8192 / 1184)

__device__ double g_acc[8];
__device__ float  g_scale[NC];
__device__ float  g_shift[NC];
__device__ unsigned g_cnt;
__device__ int g_flag;

__global__ void k_init() {
    if (threadIdx.x < 8) g_acc[threadIdx.x] = 0.0;
    if (threadIdx.x == 0) { g_cnt = 0u; g_flag = 0; }
}

__device__ __forceinline__ void cp16(char* dst_smem, const float4* src) {
    unsigned d = (unsigned)__cvta_generic_to_shared(dst_smem);
    asm volatile("cp.async.cg.shared.global [%0], [%1], 16;\n" :: "r"(d), "l"(src));
}
__device__ __forceinline__ void cp_commit() { asm volatile("cp.async.commit_group;\n"); }
__device__ __forceinline__ void cp_wait1()  { asm volatile("cp.async.wait_group 1;\n"); }
__device__ __forceinline__ void cp_wait0()  { asm volatile("cp.async.wait_group 0;\n"); }

// One 16-row chunk: 576 float4 coalesced loads, padded-pitch smem placement.
__device__ __forceinline__ void issue_chunk(char* wbuf, const float* x, size_t R, int lane) {
    const float4* src = (const float4*)(x + R * 144);
    #pragma unroll
    for (int k = 0; k < 18; k++) {
        const int r0  = (32 * k) / 36;
        const int rem = (32 * k) % 36;
        int ge  = (lane + rem) >= 36;
        int row = r0 + ge;
        int p   = lane + rem - (ge ? 36 : 0);
        cp16(wbuf + (uint32_t)row * ROW_PITCH + ((uint32_t)p << 4), src + lane + 32 * k);
    }
    cp_commit();
}

// Pool one chunk: lane l -> sample row (l&15), half (l>>4). Returns (left,right).
__device__ __forceinline__ void pool_chunk(const char* cbase, int lane, float& o0, float& o1) {
    int r = lane & 15, h = lane >> 4;
    const char* rb = cbase + (uint32_t)r * ROW_PITCH + (uint32_t)h * 288u;
    float a0 = 0.f, a1 = 0.f;
    #pragma unroll
    for (int j = 0; j < 18; j++) {
        float4 v = *(const float4*)(rb + 16 * j);
        if (j % 3 == 0)      { a0 += v.x + v.y + v.z + v.w; }
        else if (j % 3 == 1) { a0 += v.x + v.y; a1 += v.z + v.w; }
        else                 { a1 += v.x + v.y + v.z + v.w; }
    }
    o0 = a0; o1 = a1;
}

__global__ void __launch_bounds__(BLK, 1) k_persist(
    const float* __restrict__ x,
    const float* __restrict__ wts,
    const float* __restrict__ W,
    const float* __restrict__ bias,
    const float* __restrict__ gamma,
    const float* __restrict__ beta,
    float* __restrict__ out,
    int B, float invB)
{
    extern __shared__ char sbuf[];
    const int t = threadIdx.x;
    const int lane = t & 31;
    const int wid  = t >> 5;
    const int gw   = blockIdx.x * WARPS_PER_BLK + wid;   // global warp id
    char* wbuf = sbuf + wid * WARP_SMEM;

    const int totalGroups = B / GROUP_ROWS;              // 8192

    float wc[8], ws[8];
    #pragma unroll
    for (int i = 0; i < 8; i++) __sincosf(wts[i] * 0.5f, &ws[i], &wc[i]);
    float Wr[16], bi[4];
    #pragma unroll
    for (int i = 0; i < 16; i++) Wr[i] = W[i];
    #pragma unroll
    for (int i = 0; i < 4; i++)  bi[i] = bias[i];

    float lg[MAX_G][4];
    float sum0=0.f,sum1=0.f,sum2=0.f,sum3=0.f, sq0=0.f,sq1=0.f,sq2=0.f,sq3=0.f;

    if (gw < totalGroups)
        issue_chunk(wbuf, x, (size_t)gw * GROUP_ROWS, lane);

    #pragma unroll
    for (int kg = 0; kg < MAX_G; kg++) {
        int g = gw + kg * WARPS_TOTAL;
        if (g < totalGroups) {
            size_t rowbase = (size_t)g * GROUP_ROWS;

            // issue second chunk of this group, wait for first
            issue_chunk(wbuf + CHUNK_BYTES, x, rowbase + CHUNK_ROWS, lane);
            cp_wait1();
            __syncwarp();

            float uA0, uA1;
            pool_chunk(wbuf, lane, uA0, uA1);
            __syncwarp();   // buf0 reads done before refill

            // prefetch next group's first chunk into buf0
            int gn = g + WARPS_TOTAL;
            if (gn < totalGroups) {
                issue_chunk(wbuf, x, (size_t)gn * GROUP_ROWS, lane);
                cp_wait1();
            } else {
                cp_wait0();
            }
            __syncwarp();

            float uB0, uB1;
            pool_chunk(wbuf + CHUNK_BYTES, lane, uB0, uB1);

            // merge: row r top half from lane r, bottom from lane r+16 (per chunk)
            int rl = lane & 15;
            float a0 = __shfl_sync(0xFFFFFFFFu, uA0, rl);
            float a1 = __shfl_sync(0xFFFFFFFFu, uA1, rl);
            float a2 = __shfl_sync(0xFFFFFFFFu, uA0, rl + 16);
            float a3 = __shfl_sync(0xFFFFFFFFu, uA1, rl + 16);
            float b0 = __shfl_sync(0xFFFFFFFFu, uB0, rl);
            float b1 = __shfl_sync(0xFFFFFFFFu, uB1, rl);
            float b2 = __shfl_sync(0xFFFFFFFFu, uB0, rl + 16);
            float b3 = __shfl_sync(0xFFFFFFFFu, uB1, rl + 16);
            bool lo = lane < 16;       // lanes 0..15 -> chunk A rows, 16..31 -> chunk B
            float s0 = lo ? a0 : b0;   // top-left
            float s1 = lo ? a1 : b1;   // top-right
            float s2 = lo ? a2 : b2;   // bottom-left
            float s3 = lo ? a3 : b3;   // bottom-right

            // ---- circuit ----
            const float inv72 = 1.f / 72.f;
            float pc4[4], ps4[4];
            __sincosf(s0 * inv72, &ps4[0], &pc4[0]);
            __sincosf(s1 * inv72, &ps4[1], &pc4[1]);
            __sincosf(s2 * inv72, &ps4[2], &pc4[2]);
            __sincosf(s3 * inv72, &ps4[3], &pc4[3]);

            float re[DIM], im[DIM];
            #pragma unroll
            for (int k = 0; k < DIM; k++) {
                float m = ((k & 8) ? ps4[0] : pc4[0])
                        * ((k & 4) ? ps4[1] : pc4[1])
                        * ((k & 2) ? ps4[2] : pc4[2])
                        * ((k & 1) ? ps4[3] : pc4[3]);
                int pc = __popc(k) & 3;
                re[k] = (pc == 0) ? m : ((pc == 2) ? -m : 0.f);
                im[k] = (pc == 1) ? -m : ((pc == 3) ? m : 0.f);
            }
            int idx = 0;
            #pragma unroll
            for (int d = 0; d < 2; d++) {
                #pragma unroll
                for (int w = 0; w < NQ; w++) {
                    float cc = wc[idx], ss = ws[idx]; idx++;
                    int bit = 1 << (3 - w);
                    #pragma unroll
                    for (int k = 0; k < DIM; k++) {
                        if (!(k & bit)) {
                            int k1 = k | bit;
                            float r0 = re[k], r1 = re[k1];
                            re[k]  = cc * r0 - ss * r1;
                            re[k1] = ss * r0 + cc * r1;
                            float i0 = im[k], i1 = im[k1];
                            im[k]  = cc * i0 - ss * i1;
                            im[k1] = ss * i0 + cc * i1;
                        }
                    }
                }
                #pragma unroll
                for (int k = 0; k < DIM; k++) {
                    int par = (((k >> 3) & (k >> 2)) ^ ((k >> 2) & (k >> 1)) ^ ((k >> 1) & k)) & 1;
                    if (par) { re[k] = -re[k]; im[k] = -im[k]; }
                }
            }
            float q0=0.f, q1=0.f, q2=0.f, q3=0.f;
            #pragma unroll
            for (int k = 0; k < DIM; k++) {
                float p = re[k] * re[k] + im[k] * im[k];
                q0 += (k & 8) ? -p : p;
                q1 += (k & 4) ? -p : p;
                q2 += (k & 2) ? -p : p;
                q3 += (k & 1) ? -p : p;
            }
            #pragma unroll
            for (int c2 = 0; c2 < NC; c2++) {
                lg[kg][c2] = bi[c2] + q0 * Wr[c2*4+0] + q1 * Wr[c2*4+1]
                                    + q2 * Wr[c2*4+2] + q3 * Wr[c2*4+3];
            }
            sum0 += lg[kg][0]; sum1 += lg[kg][1]; sum2 += lg[kg][2]; sum3 += lg[kg][3];
            sq0 += lg[kg][0]*lg[kg][0]; sq1 += lg[kg][1]*lg[kg][1];
            sq2 += lg[kg][2]*lg[kg][2]; sq3 += lg[kg][3]*lg[kg][3];

            __syncwarp();   // buf1 reads done before next iteration refills it
        }
    }

    // ---- block reduction ----
    float red[8] = {sum0,sum1,sum2,sum3,sq0,sq1,sq2,sq3};
    #pragma unroll
    for (int off = 16; off > 0; off >>= 1) {
        #pragma unroll
        for (int j = 0; j < 8; j++)
            red[j] += __shfl_down_sync(0xFFFFFFFFu, red[j], off);
    }
    __syncthreads();
    float* rsm = (float*)sbuf;   // reuse pipeline smem
    if (lane == 0) {
        #pragma unroll
        for (int j = 0; j < 8; j++) rsm[j * WARPS_PER_BLK + wid] = red[j];
    }
    __syncthreads();
    if (t < 8) {
        float acc = 0.f;
        #pragma unroll
        for (int wgi = 0; wgi < WARPS_PER_BLK; wgi++) acc += rsm[t * WARPS_PER_BLK + wgi];
        atomicAdd(&g_acc[t], (double)acc);
        __threadfence();
    }
    __syncthreads();

    // ---- grid barrier (all 148 blocks co-resident) ----
    if (t == 0) {
        unsigned r = atomicAdd(&g_cnt, 1u);
        if (r == gridDim.x - 1u) {
            #pragma unroll
            for (int c2 = 0; c2 < NC; c2++) {
                double m = g_acc[c2] * (double)invB;
                double v = g_acc[4 + c2] * (double)invB - m * m;
                float inv = rsqrtf((float)v + 1e-5f);
                g_scale[c2] = gamma[c2] * inv;
                g_shift[c2] = beta[c2] - (float)m * inv * gamma[c2];
            }
            __threadfence();
            atomicExch(&g_flag, 1);
        } else {
            while (atomicAdd(&g_flag, 0) == 0) __nanosleep(64);
        }
    }
    __syncthreads();

    float sc[4], sh[4];
    #pragma unroll
    for (int c2 = 0; c2 < NC; c2++) {
        sc[c2] = *((volatile float*)&g_scale[c2]);
        sh[c2] = *((volatile float*)&g_shift[c2]);
    }

    // ---- coalesced normalized write ----
    float4* o4 = (float4*)out;
    #pragma unroll
    for (int kg = 0; kg < MAX_G; kg++) {
        int g = gw + kg * WARPS_TOTAL;
        if (g < totalGroups) {
            o4[(size_t)g * GROUP_ROWS + lane] =
                make_float4(lg[kg][0]*sc[0]+sh[0], lg[kg][1]*sc[1]+sh[1],
                            lg[kg][2]*sc[2]+sh[2], lg[kg][3]*sc[3]+sh[3]);
        }
    }
}

extern "C" void kernel_launch(void* const* d_in, const int* in_sizes, int n_in,
                              void* d_out, int out_size) {
    const float* x     = (const float*)d_in[0];
    const float* wts   = (const float*)d_in[1];
    const float* W     = (const float*)d_in[2];
    const float* bias  = (const float*)d_in[3];
    const float* gamma = (const float*)d_in[4];
    const float* beta  = (const float*)d_in[5];
    float* out = (float*)d_out;

    int B = in_sizes[0] / 144;    // 262144

    cudaFuncSetAttribute(k_persist, cudaFuncAttributeMaxDynamicSharedMemorySize, SMEM_BYTES);

    k_init<<<1, 32>>>();
    k_persist<<<GRID, BLK, SMEM_BYTES>>>(x, wts, W, bias, gamma, beta, out,
                                         B, 1.0f / (float)B);
}